// round 14
// baseline (speedup 1.0000x reference)
#include <cuda_runtime.h>
#include <cuda_fp16.h>
#include <cstdint>

#define IN_FEATS   128
#define HIDDEN     128
#define MAX_NODES  100000
#define NTILE      64            // node rows per GEMM tile
#define BSTR_H     136           // SMEM row stride in halfs (272 B, conflict-free ldmatrix)

// P'|Q per node: 256 halfs = 512 B.  [P+b1 (128) | Q (128)]
__device__ __align__(16) __half g_pq[MAX_NODES * 256];

__device__ __forceinline__ uint32_t smem_u32(const void* p) {
    uint32_t a;
    asm("{ .reg .u64 t; cvta.to.shared.u64 t, %1; cvt.u32.u64 %0, t; }" : "=r"(a) : "l"(p));
    return a;
}

#define LDMATRIX_X4(r0, r1, r2, r3, addr) \
    asm volatile("ldmatrix.sync.aligned.m8n8.x4.shared.b16 {%0,%1,%2,%3}, [%4];" \
                 : "=r"(r0), "=r"(r1), "=r"(r2), "=r"(r3) : "r"(addr))

#define MMA16816(c0, c1, c2, c3, a0, a1, a2, a3, b0, b1) \
    asm volatile("mma.sync.aligned.m16n8k16.row.col.f32.f16.f16.f32 " \
                 "{%0,%1,%2,%3}, {%4,%5,%6,%7}, {%8,%9}, {%0,%1,%2,%3};" \
                 : "+f"(c0), "+f"(c1), "+f"(c2), "+f"(c3) \
                 : "r"(a0), "r"(a1), "r"(a2), "r"(a3), "r"(b0), "r"(b1))

// ---------------- SMEM layout (double-buffered A, 2 CTAs/SM) ----------------
#define A_TILE_B  (NTILE * BSTR_H * 2)            // 17408 B per A buffer
#define SM_B      0                               // 256 rows x 136 halfs = 69632 B
#define SM_A0     (256 * BSTR_H * 2)              // A buffer 0
#define SM_A1     (SM_A0 + A_TILE_B)              // A buffer 1
#define SM_B1S    (SM_A1 + A_TILE_B)              // 128 f32 bias1
#define SM_TOTAL  (SM_B1S + 512)                  // 104960 B -> 2 CTAs/SM (~205 KB)

// =====================================================================
// Phase 1: PQ[100K,256] = h @ B[128k,256n] (+b1 on P cols).
// Software-pipelined: next tile's A LDGs interleave with current MMAs,
// stored into the idle buffer; one __syncthreads per tile.
// =====================================================================
__global__ void __launch_bounds__(256, 2)
pq_gemm_kernel(const float* __restrict__ h, const float* __restrict__ W1,
               const float* __restrict__ b1, int n_nodes, int n_tiles)
{
    extern __shared__ char smem[];
    const int tid = threadIdx.x;
    const int wid = tid >> 5;
    const int lid = tid & 31;
    const uint32_t sb = smem_u32(smem);

    if (tid < 128) reinterpret_cast<float*>(smem + SM_B1S)[tid] = b1[tid];

    // ---- Load + convert B (W1) into SMEM once: 256 rows x 128 halfs ----
    {
        #pragma unroll
        for (int i = 0; i < 32; i++) {
            int idx = tid + i * 256;              // 8192 float4 total
            int n2 = idx >> 5;                    // output col row 0..255
            int k  = (idx & 31) * 4;
            int wrow = n2 & 127;
            int kof  = (n2 >> 7) * 128;
            float4 v = *reinterpret_cast<const float4*>(W1 + wrow * 256 + kof + k);
            __half2* dp = reinterpret_cast<__half2*>(smem + SM_B + (n2 * BSTR_H + k) * 2);
            dp[0] = __floats2half2_rn(v.x, v.y);
            dp[1] = __floats2half2_rn(v.z, v.w);
        }
    }

    const int stride = gridDim.x;
    int t = blockIdx.x;
    if (t >= n_tiles) { __syncthreads(); return; }

    // Per-thread A-chunk geometry: idx = tid + i*256 -> row = idx>>5, k = (idx&31)*4
    const int arow_base = tid >> 5;               // row for i-th chunk elem: arow_base + i*8
    const int ak = (tid & 31) * 4;

    // ---- Prologue: load tile t into buffer 0 ----
    {
        #pragma unroll
        for (int i = 0; i < 8; i++) {
            int row = arow_base + i * 8;
            int grow = t * NTILE + row;
            if (grow >= n_nodes) grow = 0;
            float4 v = *reinterpret_cast<const float4*>(h + (size_t)grow * IN_FEATS + ak);
            __half2* dp = reinterpret_cast<__half2*>(smem + SM_A0 + (row * BSTR_H + ak) * 2);
            dp[0] = __floats2half2_rn(v.x, v.y);
            dp[1] = __floats2half2_rn(v.z, v.w);
        }
    }
    __syncthreads();

    const int wm = wid >> 2;                      // 0..1 : rows wm*32
    const int wn = wid & 3;                       // 0..3 : cols wn*64
    const int lr = lid & 15;
    const int lc = (lid >> 4) * 8;
    const int g8  = lid >> 2;
    const int tig = lid & 3;

    const uint32_t b_lane = sb + SM_B + (uint32_t)(wn * 64 + lr) * (BSTR_H * 2) + (uint32_t)lc * 2;
    const float* b1s = reinterpret_cast<const float*>(smem + SM_B1S);
    const bool is_p = (wn < 2);                   // cols < 128 => P region

    int buf = 0;
    for (; t < n_tiles; t += stride) {
        const int tn = t + stride;
        const bool pf = tn < n_tiles;
        const uint32_t abase  = sb + (buf ? SM_A1 : SM_A0);
        const uint32_t nxtoff = buf ? SM_A0 : SM_A1;
        const uint32_t a_lane = abase + (uint32_t)(wm * 32 + lr) * (BSTR_H * 2) + (uint32_t)lc * 2;

        float acc[2][8][4];
        #pragma unroll
        for (int mt = 0; mt < 2; mt++)
            #pragma unroll
            for (int nt = 0; nt < 8; nt++)
                #pragma unroll
                for (int c = 0; c < 4; c++) acc[mt][nt][c] = 0.f;

        float4 r[4];
        // --- prefetch chunk 0 (rows 0..31 of next tile) ---
        if (pf) {
            #pragma unroll
            for (int i = 0; i < 4; i++) {
                int grow = tn * NTILE + arow_base + i * 8;
                if (grow >= n_nodes) grow = 0;
                r[i] = *reinterpret_cast<const float4*>(h + (size_t)grow * IN_FEATS + ak);
            }
        }

        // --- MMA ksteps 0..3 ---
        #pragma unroll
        for (int ks = 0; ks < 4; ks++) {
            const uint32_t koff = (uint32_t)ks * 32;
            uint32_t a[2][4];
            #pragma unroll
            for (int mt = 0; mt < 2; mt++)
                LDMATRIX_X4(a[mt][0], a[mt][1], a[mt][2], a[mt][3],
                            a_lane + (uint32_t)(mt * 16 * BSTR_H * 2) + koff);
            uint32_t bf[4][4];
            #pragma unroll
            for (int ntp = 0; ntp < 4; ntp++)
                LDMATRIX_X4(bf[ntp][0], bf[ntp][1], bf[ntp][2], bf[ntp][3],
                            b_lane + (uint32_t)(ntp * 16 * BSTR_H * 2) + koff);
            #pragma unroll
            for (int mt = 0; mt < 2; mt++) {
                #pragma unroll
                for (int ntp = 0; ntp < 4; ntp++) {
                    MMA16816(acc[mt][2*ntp][0], acc[mt][2*ntp][1], acc[mt][2*ntp][2], acc[mt][2*ntp][3],
                             a[mt][0], a[mt][1], a[mt][2], a[mt][3], bf[ntp][0], bf[ntp][2]);
                    MMA16816(acc[mt][2*ntp+1][0], acc[mt][2*ntp+1][1], acc[mt][2*ntp+1][2], acc[mt][2*ntp+1][3],
                             a[mt][0], a[mt][1], a[mt][2], a[mt][3], bf[ntp][1], bf[ntp][3]);
                }
            }
        }

        // --- store chunk 0, prefetch chunk 1 ---
        if (pf) {
            #pragma unroll
            for (int i = 0; i < 4; i++) {
                int row = arow_base + i * 8;
                __half2* dp = reinterpret_cast<__half2*>(smem + nxtoff + (row * BSTR_H + ak) * 2);
                dp[0] = __floats2half2_rn(r[i].x, r[i].y);
                dp[1] = __floats2half2_rn(r[i].z, r[i].w);
            }
            #pragma unroll
            for (int i = 0; i < 4; i++) {
                int grow = tn * NTILE + arow_base + (i + 4) * 8;
                if (grow >= n_nodes) grow = 0;
                r[i] = *reinterpret_cast<const float4*>(h + (size_t)grow * IN_FEATS + ak);
            }
        }

        // --- MMA ksteps 4..7 ---
        #pragma unroll
        for (int ks = 4; ks < 8; ks++) {
            const uint32_t koff = (uint32_t)ks * 32;
            uint32_t a[2][4];
            #pragma unroll
            for (int mt = 0; mt < 2; mt++)
                LDMATRIX_X4(a[mt][0], a[mt][1], a[mt][2], a[mt][3],
                            a_lane + (uint32_t)(mt * 16 * BSTR_H * 2) + koff);
            uint32_t bf[4][4];
            #pragma unroll
            for (int ntp = 0; ntp < 4; ntp++)
                LDMATRIX_X4(bf[ntp][0], bf[ntp][1], bf[ntp][2], bf[ntp][3],
                            b_lane + (uint32_t)(ntp * 16 * BSTR_H * 2) + koff);
            #pragma unroll
            for (int mt = 0; mt < 2; mt++) {
                #pragma unroll
                for (int ntp = 0; ntp < 4; ntp++) {
                    MMA16816(acc[mt][2*ntp][0], acc[mt][2*ntp][1], acc[mt][2*ntp][2], acc[mt][2*ntp][3],
                             a[mt][0], a[mt][1], a[mt][2], a[mt][3], bf[ntp][0], bf[ntp][2]);
                    MMA16816(acc[mt][2*ntp+1][0], acc[mt][2*ntp+1][1], acc[mt][2*ntp+1][2], acc[mt][2*ntp+1][3],
                             a[mt][0], a[mt][1], a[mt][2], a[mt][3], bf[ntp][1], bf[ntp][3]);
                }
            }
        }

        // --- store chunk 1 ---
        if (pf) {
            #pragma unroll
            for (int i = 0; i < 4; i++) {
                int row = arow_base + (i + 4) * 8;
                __half2* dp = reinterpret_cast<__half2*>(smem + nxtoff + (row * BSTR_H + ak) * 2);
                dp[0] = __floats2half2_rn(r[i].x, r[i].y);
                dp[1] = __floats2half2_rn(r[i].z, r[i].w);
            }
        }

        // --- epilogue: (+b1 on P cols), fp16 store to g_pq ---
        #pragma unroll
        for (int mt = 0; mt < 2; mt++) {
            #pragma unroll
            for (int hh = 0; hh < 2; hh++) {
                int grow = t * NTILE + wm * 32 + mt * 16 + g8 + hh * 8;
                if (grow < n_nodes) {
                    #pragma unroll
                    for (int nt = 0; nt < 8; nt++) {
                        int col = wn * 64 + nt * 8 + tig * 2;
                        float v0 = acc[mt][nt][hh * 2 + 0];
                        float v1 = acc[mt][nt][hh * 2 + 1];
                        if (is_p) { v0 += b1s[col]; v1 += b1s[col + 1]; }
                        __half2 hv = __floats2half2_rn(v0, v1);
                        *reinterpret_cast<__half2*>(g_pq + (size_t)grow * 256 + col) = hv;
                    }
                }
            }
        }

        __syncthreads();   // cur reads + nxt writes complete before next iter
        buf ^= 1;
    }
}

// =====================================================================
// Phase 2: per-edge score. 8 lanes per edge, 2 edges per octet-group per
// iteration (8 edges/warp). W2 in fp32 registers. 48 regs -> 5 CTAs/SM.
// =====================================================================
__device__ __forceinline__ float dot8(uint4 p, uint4 q, float4 w0, float4 w1) {
    const __half2 z = __float2half2_rn(0.f);
    __half2 h0 = __hmax2(__hadd2(*reinterpret_cast<__half2*>(&p.x),
                                 *reinterpret_cast<__half2*>(&q.x)), z);
    __half2 h1 = __hmax2(__hadd2(*reinterpret_cast<__half2*>(&p.y),
                                 *reinterpret_cast<__half2*>(&q.y)), z);
    __half2 h2 = __hmax2(__hadd2(*reinterpret_cast<__half2*>(&p.z),
                                 *reinterpret_cast<__half2*>(&q.z)), z);
    __half2 h3 = __hmax2(__hadd2(*reinterpret_cast<__half2*>(&p.w),
                                 *reinterpret_cast<__half2*>(&q.w)), z);
    float2 f0 = __half22float2(h0);
    float2 f1 = __half22float2(h1);
    float2 f2 = __half22float2(h2);
    float2 f3 = __half22float2(h3);
    float a = f0.x * w0.x;
    a = fmaf(f0.y, w0.y, a);
    a = fmaf(f1.x, w0.z, a);
    a = fmaf(f1.y, w0.w, a);
    a = fmaf(f2.x, w1.x, a);
    a = fmaf(f2.y, w1.y, a);
    a = fmaf(f3.x, w1.z, a);
    a = fmaf(f3.y, w1.w, a);
    return a;
}

__global__ void __launch_bounds__(256)
edge_score_kernel(const int* __restrict__ src, const int* __restrict__ dst,
                  const float* __restrict__ W2, const float* __restrict__ b2,
                  float* __restrict__ out, int E)
{
    const int lane = threadIdx.x & 31;
    const int oct  = lane & 7;           // dim octet within edge
    const int sub  = lane >> 3;          // edge slot within warp (0..3)
    const int warp_gid = (blockIdx.x * blockDim.x + threadIdx.x) >> 5;
    const int nwarps = (gridDim.x * blockDim.x) >> 5;

    const float4 w2a0 = *reinterpret_cast<const float4*>(W2 + oct * 8);
    const float4 w2a1 = *reinterpret_cast<const float4*>(W2 + oct * 8 + 4);
    const float4 w2b0 = *reinterpret_cast<const float4*>(W2 + 64 + oct * 8);
    const float4 w2b1 = *reinterpret_cast<const float4*>(W2 + 64 + oct * 8 + 4);
    const float bias2 = b2[0];
    const char* pqb = reinterpret_cast<const char*>(g_pq);

    for (int base = warp_gid * 8; base < E; base += nwarps * 8) {
        int e0 = base + sub;
        int e1 = base + 4 + sub;
        bool v0 = e0 < E, v1 = e1 < E;
        int i0 = v0 ? e0 : (E - 1);
        int i1 = v1 ? e1 : (E - 1);
        int s0 = __ldg(src + i0), d0 = __ldg(dst + i0);
        int s1 = __ldg(src + i1), d1 = __ldg(dst + i1);

        const char* p0 = pqb + (size_t)s0 * 512;
        const char* q0 = pqb + (size_t)d0 * 512 + 256;
        const char* p1 = pqb + (size_t)s1 * 512;
        const char* q1 = pqb + (size_t)d1 * 512 + 256;

        // 8 independent 16B loads in flight
        uint4 pa0 = *reinterpret_cast<const uint4*>(p0 + oct * 16);
        uint4 pb0 = *reinterpret_cast<const uint4*>(p0 + 128 + oct * 16);
        uint4 qa0 = *reinterpret_cast<const uint4*>(q0 + oct * 16);
        uint4 qb0 = *reinterpret_cast<const uint4*>(q0 + 128 + oct * 16);
        uint4 pa1 = *reinterpret_cast<const uint4*>(p1 + oct * 16);
        uint4 pb1 = *reinterpret_cast<const uint4*>(p1 + 128 + oct * 16);
        uint4 qa1 = *reinterpret_cast<const uint4*>(q1 + oct * 16);
        uint4 qb1 = *reinterpret_cast<const uint4*>(q1 + 128 + oct * 16);

        float acc0 = dot8(pa0, qa0, w2a0, w2a1) + dot8(pb0, qb0, w2b0, w2b1);
        float acc1 = dot8(pa1, qa1, w2a0, w2a1) + dot8(pb1, qb1, w2b0, w2b1);

        acc0 += __shfl_xor_sync(0xFFFFFFFF, acc0, 1);
        acc1 += __shfl_xor_sync(0xFFFFFFFF, acc1, 1);
        acc0 += __shfl_xor_sync(0xFFFFFFFF, acc0, 2);
        acc1 += __shfl_xor_sync(0xFFFFFFFF, acc1, 2);
        acc0 += __shfl_xor_sync(0xFFFFFFFF, acc0, 4);
        acc1 += __shfl_xor_sync(0xFFFFFFFF, acc1, 4);

        if (oct == 0) {
            if (v0) out[e0] = 1.f / (1.f + __expf(-(acc0 + bias2)));
            if (v1) out[e1] = 1.f / (1.f + __expf(-(acc1 + bias2)));
        }
    }
}

// ---------------- Launch ----------------
extern "C" void kernel_launch(void* const* d_in, const int* in_sizes, int n_in,
                              void* d_out, int out_size) {
    const int*   src = (const int*)d_in[0];
    const int*   dst = (const int*)d_in[1];
    const float* h   = (const float*)d_in[2];
    const float* W1  = (const float*)d_in[3];
    const float* b1  = (const float*)d_in[4];
    const float* W2  = (const float*)d_in[5];
    const float* b2  = (const float*)d_in[6];
    float* out = (float*)d_out;

    const int E       = in_sizes[0];
    const int n_nodes = in_sizes[2] / IN_FEATS;

    int dev = 0, sms = 148;
    cudaGetDevice(&dev);
    cudaDeviceGetAttribute(&sms, cudaDevAttrMultiProcessorCount, dev);

    // Phase 1: pipelined full-N node GEMM, 2 CTAs per SM
    cudaFuncSetAttribute(pq_gemm_kernel, cudaFuncAttributeMaxDynamicSharedMemorySize, SM_TOTAL);
    int n_tiles = (n_nodes + NTILE - 1) / NTILE;
    int grid1 = (n_tiles < 2 * sms) ? n_tiles : 2 * sms;
    pq_gemm_kernel<<<grid1, 256, SM_TOTAL>>>(h, W1, b1, n_nodes, n_tiles);

    // Phase 2: edge scoring, 8 edges per warp; 5 CTAs/SM (single full wave)
    int grid2 = sms * 5;
    edge_score_kernel<<<grid2, 256>>>(src, dst, W2, b2, out, E);
}

// round 15
// speedup vs baseline: 1.0433x; 1.0433x over previous
#include <cuda_runtime.h>
#include <cuda_fp16.h>
#include <cstdint>

#define IN_FEATS   128
#define HIDDEN     128
#define MAX_NODES  100000
#define NTILE      64            // node rows per GEMM tile
#define BSTR_H     136           // SMEM row stride in halfs (272 B, conflict-free ldmatrix)

// P'|Q per node: 256 halfs = 512 B.  [P+b1 (128) | Q (128)]
__device__ __align__(16) __half g_pq[MAX_NODES * 256];

__device__ __forceinline__ uint32_t smem_u32(const void* p) {
    uint32_t a;
    asm("{ .reg .u64 t; cvta.to.shared.u64 t, %1; cvt.u32.u64 %0, t; }" : "=r"(a) : "l"(p));
    return a;
}

#define LDMATRIX_X4(r0, r1, r2, r3, addr) \
    asm volatile("ldmatrix.sync.aligned.m8n8.x4.shared.b16 {%0,%1,%2,%3}, [%4];" \
                 : "=r"(r0), "=r"(r1), "=r"(r2), "=r"(r3) : "r"(addr))

#define MMA16816(c0, c1, c2, c3, a0, a1, a2, a3, b0, b1) \
    asm volatile("mma.sync.aligned.m16n8k16.row.col.f32.f16.f16.f32 " \
                 "{%0,%1,%2,%3}, {%4,%5,%6,%7}, {%8,%9}, {%0,%1,%2,%3};" \
                 : "+f"(c0), "+f"(c1), "+f"(c2), "+f"(c3) \
                 : "r"(a0), "r"(a1), "r"(a2), "r"(a3), "r"(b0), "r"(b1))

// ---------------- SMEM layout (full-N GEMM, 2 CTAs/SM) ----------------
#define SM_B      0                               // 256 rows x 136 halfs = 69632 B
#define SM_A      (256 * BSTR_H * 2)              // 64 rows x 136 halfs = 17408 B
#define SM_B1S    (SM_A + NTILE * BSTR_H * 2)     // 128 f32 bias1
#define SM_TOTAL  (SM_B1S + 512)                  // 87552 B -> 2 CTAs/SM (175 KB)

// =====================================================================
// Phase 1 (full-N, 2 CTAs/SM): PQ[100K,256] = h @ B[128k,256n] (+b1 on P)
// Round-13 baseline GEMM (co-resident CTA provides latency hiding).
// =====================================================================
__global__ void __launch_bounds__(256, 2)
pq_gemm_kernel(const float* __restrict__ h, const float* __restrict__ W1,
               const float* __restrict__ b1, int n_nodes, int n_tiles)
{
    extern __shared__ char smem[];
    const int tid = threadIdx.x;
    const int wid = tid >> 5;
    const int lid = tid & 31;
    const uint32_t sb = smem_u32(smem);

    if (tid < 128) reinterpret_cast<float*>(smem + SM_B1S)[tid] = b1[tid];

    // ---- Load + convert B (W1) into SMEM once: 256 rows x 128 halfs ----
    {
        #pragma unroll
        for (int i = 0; i < 32; i++) {
            int idx = tid + i * 256;              // 8192 float4 total
            int n2 = idx >> 5;                    // output col row 0..255
            int k  = (idx & 31) * 4;
            int wrow = n2 & 127;
            int kof  = (n2 >> 7) * 128;
            float4 v = *reinterpret_cast<const float4*>(W1 + wrow * 256 + kof + k);
            __half2* dp = reinterpret_cast<__half2*>(smem + SM_B + (n2 * BSTR_H + k) * 2);
            dp[0] = __floats2half2_rn(v.x, v.y);
            dp[1] = __floats2half2_rn(v.z, v.w);
        }
    }

    const int wm = wid >> 2;                      // 0..1 : rows wm*32
    const int wn = wid & 3;                       // 0..3 : cols wn*64
    const int lr = lid & 15;
    const int lc = (lid >> 4) * 8;
    const int g8  = lid >> 2;
    const int tig = lid & 3;

    const uint32_t b_lane = sb + SM_B + (uint32_t)(wn * 64 + lr) * (BSTR_H * 2) + (uint32_t)lc * 2;
    const uint32_t a_lane = sb + SM_A + (uint32_t)(wm * 32 + lr) * (BSTR_H * 2) + (uint32_t)lc * 2;
    const float* b1s = reinterpret_cast<const float*>(smem + SM_B1S);
    const bool is_p = (wn < 2);                   // cols < 128 => P region

    for (int t = blockIdx.x; t < n_tiles; t += gridDim.x) {
        // Load A tile fp32 -> convert -> SMEM fp16 (latency hidden by co-CTA)
        #pragma unroll
        for (int i = 0; i < 8; i++) {
            int idx = tid + i * 256;
            int row = idx >> 5;
            int k   = (idx & 31) * 4;
            int grow = t * NTILE + row;
            if (grow >= n_nodes) grow = 0;        // clamp (values unused)
            float4 v = *reinterpret_cast<const float4*>(h + (size_t)grow * IN_FEATS + k);
            __half2* dp = reinterpret_cast<__half2*>(smem + SM_A + (row * BSTR_H + k) * 2);
            dp[0] = __floats2half2_rn(v.x, v.y);
            dp[1] = __floats2half2_rn(v.z, v.w);
        }
        __syncthreads();

        float acc[2][8][4];
        #pragma unroll
        for (int mt = 0; mt < 2; mt++)
            #pragma unroll
            for (int nt = 0; nt < 8; nt++)
                #pragma unroll
                for (int c = 0; c < 4; c++) acc[mt][nt][c] = 0.f;

        #pragma unroll
        for (int ks = 0; ks < 8; ks++) {
            const uint32_t koff = (uint32_t)ks * 32;
            uint32_t a[2][4];
            #pragma unroll
            for (int mt = 0; mt < 2; mt++)
                LDMATRIX_X4(a[mt][0], a[mt][1], a[mt][2], a[mt][3],
                            a_lane + (uint32_t)(mt * 16 * BSTR_H * 2) + koff);
            uint32_t bf[4][4];
            #pragma unroll
            for (int ntp = 0; ntp < 4; ntp++)
                LDMATRIX_X4(bf[ntp][0], bf[ntp][1], bf[ntp][2], bf[ntp][3],
                            b_lane + (uint32_t)(ntp * 16 * BSTR_H * 2) + koff);
            #pragma unroll
            for (int mt = 0; mt < 2; mt++) {
                #pragma unroll
                for (int ntp = 0; ntp < 4; ntp++) {
                    MMA16816(acc[mt][2*ntp][0], acc[mt][2*ntp][1], acc[mt][2*ntp][2], acc[mt][2*ntp][3],
                             a[mt][0], a[mt][1], a[mt][2], a[mt][3], bf[ntp][0], bf[ntp][2]);
                    MMA16816(acc[mt][2*ntp+1][0], acc[mt][2*ntp+1][1], acc[mt][2*ntp+1][2], acc[mt][2*ntp+1][3],
                             a[mt][0], a[mt][1], a[mt][2], a[mt][3], bf[ntp][1], bf[ntp][3]);
                }
            }
        }

        // epilogue: (+b1 on P cols), fp16 store to g_pq
        #pragma unroll
        for (int mt = 0; mt < 2; mt++) {
            #pragma unroll
            for (int hh = 0; hh < 2; hh++) {
                int grow = t * NTILE + wm * 32 + mt * 16 + g8 + hh * 8;
                if (grow < n_nodes) {
                    #pragma unroll
                    for (int nt = 0; nt < 8; nt++) {
                        int col = wn * 64 + nt * 8 + tig * 2;
                        float v0 = acc[mt][nt][hh * 2 + 0];
                        float v1 = acc[mt][nt][hh * 2 + 1];
                        if (is_p) { v0 += b1s[col]; v1 += b1s[col + 1]; }
                        __half2 hv = __floats2half2_rn(v0, v1);
                        *reinterpret_cast<__half2*>(g_pq + (size_t)grow * 256 + col) = hv;
                    }
                }
            }
        }
        __syncthreads();   // all LDSM reads of A done before next tile's STS
    }
}

// =====================================================================
// Phase 2: per-edge score. 8 lanes per edge, 2 edges per octet-group per
// iteration (8 edges/warp). W2 in fp32 regs; 32-bit PQ offsets + forced
// 42-reg budget to reach 6 CTAs/SM.
// =====================================================================
__device__ __forceinline__ float dot8(uint4 p, uint4 q, float4 w0, float4 w1) {
    const __half2 z = __float2half2_rn(0.f);
    __half2 h0 = __hmax2(__hadd2(*reinterpret_cast<__half2*>(&p.x),
                                 *reinterpret_cast<__half2*>(&q.x)), z);
    __half2 h1 = __hmax2(__hadd2(*reinterpret_cast<__half2*>(&p.y),
                                 *reinterpret_cast<__half2*>(&q.y)), z);
    __half2 h2 = __hmax2(__hadd2(*reinterpret_cast<__half2*>(&p.z),
                                 *reinterpret_cast<__half2*>(&q.z)), z);
    __half2 h3 = __hmax2(__hadd2(*reinterpret_cast<__half2*>(&p.w),
                                 *reinterpret_cast<__half2*>(&q.w)), z);
    float2 f0 = __half22float2(h0);
    float2 f1 = __half22float2(h1);
    float2 f2 = __half22float2(h2);
    float2 f3 = __half22float2(h3);
    float a = f0.x * w0.x;
    a = fmaf(f0.y, w0.y, a);
    a = fmaf(f1.x, w0.z, a);
    a = fmaf(f1.y, w0.w, a);
    a = fmaf(f2.x, w1.x, a);
    a = fmaf(f2.y, w1.y, a);
    a = fmaf(f3.x, w1.z, a);
    a = fmaf(f3.y, w1.w, a);
    return a;
}

__global__ void __launch_bounds__(256, 6)
edge_score_kernel(const int* __restrict__ src, const int* __restrict__ dst,
                  const float* __restrict__ W2, const float* __restrict__ b2,
                  float* __restrict__ out, int E)
{
    const int lane = threadIdx.x & 31;
    const int oct  = lane & 7;           // dim octet within edge
    const int sub  = lane >> 3;          // edge slot within warp (0..3)
    const int warp_gid = (blockIdx.x * blockDim.x + threadIdx.x) >> 5;
    const int nwarps = (gridDim.x * blockDim.x) >> 5;

    const float4 w2a0 = *reinterpret_cast<const float4*>(W2 + oct * 8);
    const float4 w2a1 = *reinterpret_cast<const float4*>(W2 + oct * 8 + 4);
    const float4 w2b0 = *reinterpret_cast<const float4*>(W2 + 64 + oct * 8);
    const float4 w2b1 = *reinterpret_cast<const float4*>(W2 + 64 + oct * 8 + 4);
    const float bias2 = b2[0];
    const char* pqb = reinterpret_cast<const char*>(g_pq);
    const uint32_t octb = (uint32_t)(oct * 16);

    for (int base = warp_gid * 8; base < E; base += nwarps * 8) {
        int e0 = base + sub;
        int e1 = base + 4 + sub;
        bool v0 = e0 < E, v1 = e1 < E;
        int i0 = v0 ? e0 : (E - 1);
        int i1 = v1 ? e1 : (E - 1);

        // 32-bit byte offsets into g_pq (node*512 < 2^31): 4 regs, not 8 ptr pairs
        uint32_t op0 = (uint32_t)__ldg(src + i0) * 512u + octb;
        uint32_t oq0 = (uint32_t)__ldg(dst + i0) * 512u + 256u + octb;
        uint32_t op1 = (uint32_t)__ldg(src + i1) * 512u + octb;
        uint32_t oq1 = (uint32_t)__ldg(dst + i1) * 512u + 256u + octb;

        // 8 independent 16B loads in flight
        uint4 pa0 = *reinterpret_cast<const uint4*>(pqb + op0);
        uint4 pb0 = *reinterpret_cast<const uint4*>(pqb + op0 + 128);
        uint4 qa0 = *reinterpret_cast<const uint4*>(pqb + oq0);
        uint4 qb0 = *reinterpret_cast<const uint4*>(pqb + oq0 + 128);
        uint4 pa1 = *reinterpret_cast<const uint4*>(pqb + op1);
        uint4 pb1 = *reinterpret_cast<const uint4*>(pqb + op1 + 128);
        uint4 qa1 = *reinterpret_cast<const uint4*>(pqb + oq1);
        uint4 qb1 = *reinterpret_cast<const uint4*>(pqb + oq1 + 128);

        float acc0 = dot8(pa0, qa0, w2a0, w2a1) + dot8(pb0, qb0, w2b0, w2b1);
        float acc1 = dot8(pa1, qa1, w2a0, w2a1) + dot8(pb1, qb1, w2b0, w2b1);

        acc0 += __shfl_xor_sync(0xFFFFFFFF, acc0, 1);
        acc1 += __shfl_xor_sync(0xFFFFFFFF, acc1, 1);
        acc0 += __shfl_xor_sync(0xFFFFFFFF, acc0, 2);
        acc1 += __shfl_xor_sync(0xFFFFFFFF, acc1, 2);
        acc0 += __shfl_xor_sync(0xFFFFFFFF, acc0, 4);
        acc1 += __shfl_xor_sync(0xFFFFFFFF, acc1, 4);

        if (oct == 0) {
            if (v0) out[e0] = 1.f / (1.f + __expf(-(acc0 + bias2)));
            if (v1) out[e1] = 1.f / (1.f + __expf(-(acc1 + bias2)));
        }
    }
}

// ---------------- Launch ----------------
extern "C" void kernel_launch(void* const* d_in, const int* in_sizes, int n_in,
                              void* d_out, int out_size) {
    const int*   src = (const int*)d_in[0];
    const int*   dst = (const int*)d_in[1];
    const float* h   = (const float*)d_in[2];
    const float* W1  = (const float*)d_in[3];
    const float* b1  = (const float*)d_in[4];
    const float* W2  = (const float*)d_in[5];
    const float* b2  = (const float*)d_in[6];
    float* out = (float*)d_out;

    const int E       = in_sizes[0];
    const int n_nodes = in_sizes[2] / IN_FEATS;

    int dev = 0, sms = 148;
    cudaGetDevice(&dev);
    cudaDeviceGetAttribute(&sms, cudaDevAttrMultiProcessorCount, dev);

    // Phase 1: full-N node GEMM, 2 CTAs per SM (round-13 baseline)
    cudaFuncSetAttribute(pq_gemm_kernel, cudaFuncAttributeMaxDynamicSharedMemorySize, SM_TOTAL);
    int n_tiles = (n_nodes + NTILE - 1) / NTILE;
    int grid1 = (n_tiles < 2 * sms) ? n_tiles : 2 * sms;
    pq_gemm_kernel<<<grid1, 256, SM_TOTAL>>>(h, W1, b1, n_nodes, n_tiles);

    // Phase 2: edge scoring, 8 edges per warp; 6 CTAs/SM (single full wave)
    int grid2 = sms * 6;
    edge_score_kernel<<<grid2, 256>>>(src, dst, W2, b2, out, E);
}